// round 4
// baseline (speedup 1.0000x reference)
#include <cuda_runtime.h>
#include <cuda_bf16.h>
#include <cstdint>

typedef unsigned int u32;
typedef unsigned long long u64;

#define A_NUM   3
#define SHW     (32 * 128 * 128)            // 2^19
#define N_SC    (A_NUM * SHW)               // 1572864
#define N_SC4   (N_SC / 4)                  // 393216
#define PRE_TOPN  2000
#define POST_TOPN 300
#define NMS_T     0.7f
#define MASK_COLS 32
#define CAND_CAP  8192

#define NBLK 148
#define NTHR 1024
#define GSTRIDE (NBLK * NTHR)               // 151552
// N_SC4 = 2*GSTRIDE + 90112 ; block-uniform third load for bid < 88
#define THIRD_BLKS 88

__device__ u32  g_hist1[4096];
__device__ u32  g_hist2[4096];
__device__ int  g_ccount;
__device__ u64  g_cand[CAND_CAP];
__device__ int  g_order[PRE_TOPN];
__device__ float g_score[PRE_TOPN];
__device__ float g_bx[PRE_TOPN * 6];
__device__ float g_vol[PRE_TOPN];
__device__ u64  g_invalid[32];
__device__ u64  g_mask[PRE_TOPN * MASK_COLS];
__device__ u32  g_barc;
__device__ u32  g_barg;

__device__ __forceinline__ u32 fkey(float f) {
    u32 b = __float_as_uint(f);
    return b ^ ((b & 0x80000000u) ? 0xFFFFFFFFu : 0x80000000u);
}

__device__ __forceinline__ void gbar() {
    __syncthreads();
    if (threadIdx.x == 0) {
        u32 gen = *((volatile u32*)&g_barg);
        __threadfence();
        if (atomicAdd(&g_barc, 1u) == NBLK - 1) {
            g_barc = 0;
            __threadfence();
            atomicExch(&g_barg, gen + 1);
        } else {
            while (*((volatile u32*)&g_barg) == gen) __nanosleep(32);
        }
        __threadfence();
    }
    __syncthreads();
}

// All-blocks histogram select: find bucket containing the `target`-th element
// counting from the top of a 4096-bucket histogram. Read-only. Results
// broadcast to all threads of the block via sres[0]=bucket, sres[1]=count
// strictly above that bucket. Must be called by all 1024 threads.
__device__ __forceinline__ void find_bucket(const u32* __restrict__ hist, u32 target,
                                            u32* ws, u32* sres,
                                            u32& out_b, u32& out_above) {
    const int tid = threadIdx.x, lane = tid & 31, wid = tid >> 5;
    const int base = 4095 - tid * 4;
    u32 v0 = hist[base], v1 = hist[base - 1], v2 = hist[base - 2], v3 = hist[base - 3];
    u32 s = v0 + v1 + v2 + v3;
    u32 x = s;
#pragma unroll
    for (int off = 1; off < 32; off <<= 1) {
        u32 y = __shfl_up_sync(0xFFFFFFFFu, x, off);
        if (lane >= off) x += y;
    }
    if (lane == 31) ws[wid] = x;
    __syncthreads();
    if (wid == 0) {
        u32 wv = ws[lane];
        u32 wx = wv;
#pragma unroll
        for (int off = 1; off < 32; off <<= 1) {
            u32 y = __shfl_up_sync(0xFFFFFFFFu, wx, off);
            if (lane >= off) wx += y;
        }
        ws[lane] = wx - wv;   // exclusive
    }
    __syncthreads();
    u32 incl = x + ws[wid];
    u32 excl = incl - s;
    if (excl < target && incl >= target) {
        u32 cum = excl;
        u32 vv[4] = {v0, v1, v2, v3};
#pragma unroll
        for (int k = 0; k < 4; k++) {
            if (cum + vv[k] >= target) { sres[0] = (u32)(base - k); sres[1] = cum; break; }
            cum += vv[k];
        }
    }
    __syncthreads();
    out_b = sres[0];
    out_above = sres[1];
    __syncthreads();
}

#define SM_BYTES 34048
__global__ void __launch_bounds__(NTHR, 1)
k_all(const float4* __restrict__ sc4, const float* __restrict__ deltas,
      const float* __restrict__ imi, const float* __restrict__ anchors,
      float* __restrict__ out) {
    __shared__ __align__(16) char smraw[SM_BYTES];
    __shared__ u32 ws[32];
    __shared__ u32 sres[2];
    const int tid = threadIdx.x;
    const int bid = blockIdx.x;
    const int lane = tid & 31;
    const int i0 = bid * NTHR + tid;
    const bool third = (bid < THIRD_BLKS);

    // =========== P1: coarse 12-bit histogram of all scores ===========
    {
        u32* sh = (u32*)smraw;
        for (int i = tid; i < 4096; i += NTHR) sh[i] = 0u;
        __syncthreads();
        float4 v0 = sc4[i0];
        float4 v1 = sc4[i0 + GSTRIDE];
        float4 v2 = third ? sc4[i0 + 2 * GSTRIDE] : make_float4(0, 0, 0, 0);
        float f[12] = {v0.x, v0.y, v0.z, v0.w, v1.x, v1.y, v1.z, v1.w,
                       v2.x, v2.y, v2.z, v2.w};
        int nf = third ? 12 : 8;
#pragma unroll
        for (int j = 0; j < 12; j++) {
            if (j >= nf) break;            // block-uniform
            u32 b = fkey(f[j]) >> 20;
            u32 m = __match_any_sync(0xFFFFFFFFu, b);
            if ((__ffs(m) - 1) == lane) atomicAdd(&sh[b], __popc(m));
        }
        __syncthreads();
        for (int i = tid; i < 4096; i += NTHR)
            if (sh[i]) atomicAdd(&g_hist1[i], sh[i]);
    }
    gbar();   // G1

    // =========== P2: find1 (all blocks) + refined histogram ===========
    u32 b1, above1;
    {
        u32* sh = (u32*)smraw;
        for (int i = tid; i < 4096; i += NTHR) sh[i] = 0u;
        __syncthreads();
        find_bucket(g_hist1, PRE_TOPN, ws, sres, b1, above1);
        float4 v0 = sc4[i0];
        float4 v1 = sc4[i0 + GSTRIDE];
        float4 v2 = third ? sc4[i0 + 2 * GSTRIDE] : make_float4(0, 0, 0, 0);
        float f[12] = {v0.x, v0.y, v0.z, v0.w, v1.x, v1.y, v1.z, v1.w,
                       v2.x, v2.y, v2.z, v2.w};
        int nf = third ? 12 : 8;
#pragma unroll
        for (int j = 0; j < 12; j++) {
            if (j >= nf) break;
            u32 k = fkey(f[j]);
            if ((k >> 20) == b1) atomicAdd(&sh[(k >> 8) & 0xFFFu], 1u);
        }
        __syncthreads();
        for (int i = tid; i < 4096; i += NTHR)
            if (sh[i]) atomicAdd(&g_hist2[i], sh[i]);
    }
    gbar();   // G2

    // =========== P3: find2 (all blocks) + gather; init g_invalid ===========
    {
        u32 b2, dummy;
        find_bucket(g_hist2, PRE_TOPN - above1, ws, sres, b2, dummy);
        u32 thr = (b1 << 12) | b2;
        if (bid == 0 && tid < 32)
            g_invalid[tid] = (tid == 31) ? 0xFFFFFFFFFFFF0000ULL : 0ULL;
        float4 v0 = sc4[i0];
        float4 v1 = sc4[i0 + GSTRIDE];
        float4 v2 = third ? sc4[i0 + 2 * GSTRIDE] : make_float4(0, 0, 0, 0);
        float f[12] = {v0.x, v0.y, v0.z, v0.w, v1.x, v1.y, v1.z, v1.w,
                       v2.x, v2.y, v2.z, v2.w};
        int bidx[3] = {i0 * 4, (i0 + GSTRIDE) * 4, (i0 + 2 * GSTRIDE) * 4};
        int nf = third ? 12 : 8;
#pragma unroll
        for (int j = 0; j < 12; j++) {
            if (j >= nf) break;
            u32 k = fkey(f[j]);
            bool pred = ((k >> 8) >= thr);
            u32 bal = __ballot_sync(0xFFFFFFFFu, pred);
            if (bal) {
                int leader = __ffs(bal) - 1;
                int posb = 0;
                if (lane == leader) posb = atomicAdd(&g_ccount, __popc(bal));
                posb = __shfl_sync(0xFFFFFFFFu, posb, leader);
                if (pred) {
                    int m = bidx[j >> 2] + (j & 3);
                    int a = m >> 19;
                    int shw = m & (SHW - 1);
                    u32 r = (u32)(shw * A_NUM + a);
                    int pos = posb + __popc(bal & ((1u << lane) - 1u));
                    if (pos < CAND_CAP)
                        g_cand[pos] = ((u64)k << 32) | (0xFFFFFFFFu - r);
                }
            }
        }
    }
    gbar();   // G3

    // =========== P4: rank + box decode; idle blocks zero mask/hists ===========
    {
        int cc = g_ccount; if (cc > CAND_CAP) cc = CAND_CAP;
        int bact = (cc + NTHR - 1) / NTHR;
        if (bid < bact) {
            u64* st = (u64*)smraw;   // 2048 u64
            int t = bid * NTHR + tid;
            u64 myk = (t < cc) ? g_cand[t] : 0ULL;
            int rank = 0;
            for (int b0 = 0; b0 < cc; b0 += 2048) {
                int n = min(2048, cc - b0);
                for (int j = tid; j < n; j += NTHR) st[j] = g_cand[b0 + j];
                __syncthreads();
                if (t < cc)
                    for (int j = 0; j < n; j++) rank += (st[j] > myk);
                __syncthreads();
            }
            if (t < cc && rank < PRE_TOPN) {
                u32 k = (u32)(myk >> 32);
                u32 r = 0xFFFFFFFFu - (u32)(myk & 0xFFFFFFFFu);
                g_order[rank] = (int)r;
                u32 bits = (k & 0x80000000u) ? (k ^ 0x80000000u) : ~k;
                g_score[rank] = __uint_as_float(bits);
                int a   = (int)(r % A_NUM);
                int shw = (int)(r / A_NUM);
                int w = shw & 127, h = (shw >> 7) & 127, sd = shw >> 14;
                float sx = (float)w * 4.0f, sy = (float)h * 4.0f, sz = (float)sd * 4.0f;
                float ax1 = sx + anchors[a * 6 + 0];
                float ay1 = sy + anchors[a * 6 + 1];
                float az1 = sz + anchors[a * 6 + 2];
                float ax2 = sx + anchors[a * 6 + 3];
                float ay2 = sy + anchors[a * 6 + 4];
                float az2 = sz + anchors[a * 6 + 5];
                float wA = ax2 - ax1 + 1.0f, hA = ay2 - ay1 + 1.0f, dA = az2 - az1 + 1.0f;
                float cx = ax1 + 0.5f * wA, cy = ay1 + 0.5f * hA, cz = az1 + 0.5f * dA;
                const float* dp = deltas + (size_t)(a * 6) * SHW + shw;
                float d0 = dp[0 * SHW], d1 = dp[1 * SHW], d2 = dp[2 * SHW];
                float d3 = dp[3 * SHW], d4 = dp[4 * SHW], d5 = dp[5 * SHW];
                float pcx = d0 * wA + cx, pcy = d1 * hA + cy, pcz = d2 * dA + cz;
                float pw = expf(d3) * wA, ph = expf(d4) * hA, pd = expf(d5) * dA;
                float slices = imi[0], height = imi[1], width = imi[2], scale = imi[3];
                float x1 = fminf(fmaxf(pcx - 0.5f * pw, 0.0f), width  - 1.0f);
                float y1 = fminf(fmaxf(pcy - 0.5f * ph, 0.0f), height - 1.0f);
                float z1 = fminf(fmaxf(pcz - 0.5f * pd, 0.0f), slices - 1.0f);
                float x2 = fminf(fmaxf(pcx + 0.5f * pw - 1.0f, 0.0f), width  - 1.0f);
                float y2 = fminf(fmaxf(pcy + 0.5f * ph - 1.0f, 0.0f), height - 1.0f);
                float z2 = fminf(fmaxf(pcz + 0.5f * pd - 1.0f, 0.0f), slices - 1.0f);
                g_bx[rank * 6 + 0] = x1; g_bx[rank * 6 + 1] = y1; g_bx[rank * 6 + 2] = z1;
                g_bx[rank * 6 + 3] = x2; g_bx[rank * 6 + 4] = y2; g_bx[rank * 6 + 5] = z2;
                g_vol[rank] = (x2 - x1 + 1.0f) * (y2 - y1 + 1.0f) * (z2 - z1 + 1.0f);
                float ss = x2 - x1 + 1.0f;
                float xc = x1 + ss * 0.5f, yc = y1 + ss * 0.5f, zc = z1 + ss * 0.5f;
                bool valid = (ss >= 8.0f * scale) && (xc < width) && (yc < height) && (zc < slices);
                if (!valid) atomicOr(&g_invalid[rank >> 6], 1ULL << (rank & 63));
            }
        } else {
            // zero mask (64000 u64) + hist1 + hist2 (8192 u32) for next replay
            int zb = bid - bact;
            int nzb = NBLK - bact;
            int zt = zb * NTHR + tid;
            int zstride = nzb * NTHR;
            for (int k = zt; k < PRE_TOPN * MASK_COLS; k += zstride) g_mask[k] = 0ULL;
            for (int k = zt; k < 4096; k += zstride) { g_hist1[k] = 0u; g_hist2[k] = 0u; }
        }
    }
    gbar();   // G4

    // =========== P5: IoU suppression masks (one pass) ===========
    {
        if (bid == 0 && tid == 0) g_ccount = 0;   // reset for next replay
        float* cbb = (float*)smraw + (tid >> 6) * 64 * 7;
        int grp = tid >> 6, lt = tid & 63;
        int tile = bid * 16 + grp;
        int rb = tile >> 5, cbi = tile & 31;
        bool act = (tile < 1024) && (cbi >= rb);
        if (act) {
            int j = cbi * 64 + lt;
            if (j < PRE_TOPN) {
#pragma unroll
                for (int q = 0; q < 6; q++) cbb[lt * 7 + q] = g_bx[j * 6 + q];
                cbb[lt * 7 + 6] = g_vol[j];
            }
        }
        __syncthreads();
        if (act) {
            int i = rb * 64 + lt;
            if (i < PRE_TOPN) {
                float x1 = g_bx[i * 6 + 0], y1 = g_bx[i * 6 + 1], z1 = g_bx[i * 6 + 2];
                float x2 = g_bx[i * 6 + 3], y2 = g_bx[i * 6 + 4], z2 = g_bx[i * 6 + 5];
                float vi = g_vol[i];
                u64 word = 0ULL;
                int jn = min(64, PRE_TOPN - cbi * 64);
                for (int jj = 0; jj < jn; jj++) {
                    int jg = cbi * 64 + jj;
                    if (jg <= i) continue;
                    const float* cj = cbb + jj * 7;
                    float iw  = fminf(x2, cj[3]) - fmaxf(x1, cj[0]) + 1.0f;
                    float ih  = fminf(y2, cj[4]) - fmaxf(y1, cj[1]) + 1.0f;
                    float idd = fminf(z2, cj[5]) - fmaxf(z1, cj[2]) + 1.0f;
                    iw = fmaxf(iw, 0.0f); ih = fmaxf(ih, 0.0f); idd = fmaxf(idd, 0.0f);
                    float inter = iw * ih * idd;
                    float iou = inter / (vi + cj[6] - inter);
                    if (iou > NMS_T) word |= (1ULL << jj);
                }
                g_mask[i * MASK_COLS + cbi] = word;
            }
        }
    }
    gbar();   // G5

    // =========== P6: greedy NMS + output (block 0) ===========
    if (bid != 0) return;
    {
        u64* buf    = (u64*)smraw;                 // 2 x 2048 u64 = 32KB
        int* keep_s = (int*)(smraw + 32768);       // 300 ints
        int* s_nk   = (int*)(smraw + 32768 + 1200);
        int* s_flag = (int*)(smraw + 32768 + 1204);
        if (tid == 0) { *s_flag = 0; *s_nk = 0; }
        u64 remv = 0ULL;
        if (tid < 32) remv = g_invalid[tid];
        for (int k = tid; k < 64 * MASK_COLS; k += NTHR) buf[k] = g_mask[k];
        __syncthreads();

        int nk = 0;
        for (int c = 0; c < MASK_COLS; c++) {
            if (tid >= 32 && c + 1 < MASK_COLS) {
                int r0n = (c + 1) * 64;
                int rnn = min(64, PRE_TOPN - r0n);
                u64* dst = buf + ((c + 1) & 1) * 2048;
                for (int k = tid - 32; k < rnn * MASK_COLS; k += (NTHR - 32))
                    dst[k] = g_mask[r0n * MASK_COLS + k];
            }
            if (tid < 32) {
                const u64* sb = buf + (c & 1) * 2048;
                u64 cur = __shfl_sync(0xFFFFFFFFu, remv, c);
                u64 pend = ~cur;
                while (pend && nk < POST_TOPN) {
                    int b = __ffsll((long long)pend) - 1;
                    if (tid == 0) keep_s[nk] = c * 64 + b;
                    nk++;
                    u64 m  = sb[b * MASK_COLS + tid];
                    u64 mc = sb[b * MASK_COLS + c];
                    remv |= m;
                    pend &= ~mc;
                    pend &= ~(1ULL << b);
                }
                if (tid == 0 && (nk >= POST_TOPN || c == MASK_COLS - 1)) {
                    *s_nk = nk; *s_flag = 1;
                }
            }
            __syncthreads();
            if (*s_flag) break;
        }

        int nkf = *s_nk;
        float* rois = out;
        float* sc   = out + POST_TOPN * 7;
        float* ki   = out + POST_TOPN * 7 + POST_TOPN;
        float* sv   = out + POST_TOPN * 7 + 2 * POST_TOPN;
        for (int p = tid; p < POST_TOPN; p += NTHR) {
            if (p < nkf) {
                int i = keep_s[p];
                rois[p * 7 + 0] = 0.0f;
#pragma unroll
                for (int q = 0; q < 6; q++) rois[p * 7 + 1 + q] = g_bx[i * 6 + q];
                sc[p] = g_score[i];
                ki[p] = (float)g_order[i];
                sv[p] = 1.0f;
            } else {
#pragma unroll
                for (int q = 0; q < 7; q++) rois[p * 7 + q] = 0.0f;
                sc[p] = 0.0f;
                ki[p] = -1.0f;
                sv[p] = 0.0f;
            }
        }
    }
}

extern "C" void kernel_launch(void* const* d_in, const int* in_sizes, int n_in,
                              void* d_out, int out_size) {
    const float4* scores = (const float4*)d_in[0];
    const float*  deltas = (const float*)d_in[1];
    const float*  im_info = (const float*)d_in[2];
    const float*  anchors = (const float*)d_in[3];
    float* out = (float*)d_out;
    k_all<<<NBLK, NTHR>>>(scores, deltas, im_info, anchors, out);
    (void)in_sizes; (void)n_in; (void)out_size;
}

// round 5
// speedup vs baseline: 1.6082x; 1.6082x over previous
#include <cuda_runtime.h>
#include <cuda_bf16.h>
#include <cstdint>

typedef unsigned int u32;
typedef unsigned long long u64;

#define A_NUM   3
#define SHW     (32 * 128 * 128)            // 2^19
#define N_SC    (A_NUM * SHW)               // 1572864
#define N_SC4   (N_SC / 4)                  // 393216
#define PRE_TOPN  2000
#define POST_TOPN 300
#define NMS_T     0.7f
#define MASK_COLS 32
#define CAND_CAP  8192
#define CPB       16                        // candidates ranked per block

#define NBLK 148
#define NTHR 1024
#define GSTRIDE (NBLK * NTHR)               // 151552
#define THIRD_BLKS 88                       // N_SC4 = 2*GSTRIDE + 88*1024

__device__ u32  g_hist1[4096];
__device__ u32  g_hist2[4096];
__device__ int  g_ccount;
__device__ u64  g_cand[CAND_CAP];
__device__ int  g_order[PRE_TOPN];
__device__ float g_score[PRE_TOPN];
__device__ float g_bx[PRE_TOPN * 6];
__device__ float g_vol[PRE_TOPN];
__device__ u64  g_invalid[32];
__device__ u64  g_mask[PRE_TOPN * MASK_COLS];
__device__ u32  g_barc;
__device__ u32  g_barg;

__device__ __forceinline__ u32 fkey(float f) {
    u32 b = __float_as_uint(f);
    return b ^ ((b & 0x80000000u) ? 0xFFFFFFFFu : 0x80000000u);
}

__device__ __forceinline__ void gbar() {
    __syncthreads();
    if (threadIdx.x == 0) {
        u32 gen = *((volatile u32*)&g_barg);
        __threadfence();
        if (atomicAdd(&g_barc, 1u) == NBLK - 1) {
            g_barc = 0;
            __threadfence();
            atomicExch(&g_barg, gen + 1);
        } else {
            while (*((volatile u32*)&g_barg) == gen) __nanosleep(32);
        }
        __threadfence();
    }
    __syncthreads();
}

// All-blocks histogram select (read-only): bucket containing `target`-th
// element from the top of a 4096-bucket histogram; broadcast via sres.
__device__ __forceinline__ void find_bucket(const u32* __restrict__ hist, u32 target,
                                            u32* ws, u32* sres,
                                            u32& out_b, u32& out_above) {
    const int tid = threadIdx.x, lane = tid & 31, wid = tid >> 5;
    const int base = 4095 - tid * 4;
    u32 v0 = hist[base], v1 = hist[base - 1], v2 = hist[base - 2], v3 = hist[base - 3];
    u32 s = v0 + v1 + v2 + v3;
    u32 x = s;
#pragma unroll
    for (int off = 1; off < 32; off <<= 1) {
        u32 y = __shfl_up_sync(0xFFFFFFFFu, x, off);
        if (lane >= off) x += y;
    }
    if (lane == 31) ws[wid] = x;
    __syncthreads();
    if (wid == 0) {
        u32 wv = ws[lane];
        u32 wx = wv;
#pragma unroll
        for (int off = 1; off < 32; off <<= 1) {
            u32 y = __shfl_up_sync(0xFFFFFFFFu, wx, off);
            if (lane >= off) wx += y;
        }
        ws[lane] = wx - wv;
    }
    __syncthreads();
    u32 incl = x + ws[wid];
    u32 excl = incl - s;
    if (excl < target && incl >= target) {
        u32 cum = excl;
        u32 vv[4] = {v0, v1, v2, v3};
#pragma unroll
        for (int k = 0; k < 4; k++) {
            if (cum + vv[k] >= target) { sres[0] = (u32)(base - k); sres[1] = cum; break; }
            cum += vv[k];
        }
    }
    __syncthreads();
    out_b = sres[0];
    out_above = sres[1];
    __syncthreads();
}

__device__ __forceinline__ void decode_box(u64 myk, int rank,
                                           const float* __restrict__ deltas,
                                           const float* __restrict__ imi,
                                           const float* __restrict__ anchors) {
    u32 k = (u32)(myk >> 32);
    u32 r = 0xFFFFFFFFu - (u32)(myk & 0xFFFFFFFFu);
    g_order[rank] = (int)r;
    u32 bits = (k & 0x80000000u) ? (k ^ 0x80000000u) : ~k;
    g_score[rank] = __uint_as_float(bits);
    int a   = (int)(r % A_NUM);
    int shw = (int)(r / A_NUM);
    int w = shw & 127, h = (shw >> 7) & 127, sd = shw >> 14;
    float sx = (float)w * 4.0f, sy = (float)h * 4.0f, sz = (float)sd * 4.0f;
    float ax1 = sx + anchors[a * 6 + 0];
    float ay1 = sy + anchors[a * 6 + 1];
    float az1 = sz + anchors[a * 6 + 2];
    float ax2 = sx + anchors[a * 6 + 3];
    float ay2 = sy + anchors[a * 6 + 4];
    float az2 = sz + anchors[a * 6 + 5];
    float wA = ax2 - ax1 + 1.0f, hA = ay2 - ay1 + 1.0f, dA = az2 - az1 + 1.0f;
    float cx = ax1 + 0.5f * wA, cy = ay1 + 0.5f * hA, cz = az1 + 0.5f * dA;
    const float* dp = deltas + (size_t)(a * 6) * SHW + shw;
    float d0 = dp[0 * SHW], d1 = dp[1 * SHW], d2 = dp[2 * SHW];
    float d3 = dp[3 * SHW], d4 = dp[4 * SHW], d5 = dp[5 * SHW];
    float pcx = d0 * wA + cx, pcy = d1 * hA + cy, pcz = d2 * dA + cz;
    float pw = expf(d3) * wA, ph = expf(d4) * hA, pd = expf(d5) * dA;
    float slices = imi[0], height = imi[1], width = imi[2], scale = imi[3];
    float x1 = fminf(fmaxf(pcx - 0.5f * pw, 0.0f), width  - 1.0f);
    float y1 = fminf(fmaxf(pcy - 0.5f * ph, 0.0f), height - 1.0f);
    float z1 = fminf(fmaxf(pcz - 0.5f * pd, 0.0f), slices - 1.0f);
    float x2 = fminf(fmaxf(pcx + 0.5f * pw - 1.0f, 0.0f), width  - 1.0f);
    float y2 = fminf(fmaxf(pcy + 0.5f * ph - 1.0f, 0.0f), height - 1.0f);
    float z2 = fminf(fmaxf(pcz + 0.5f * pd - 1.0f, 0.0f), slices - 1.0f);
    g_bx[rank * 6 + 0] = x1; g_bx[rank * 6 + 1] = y1; g_bx[rank * 6 + 2] = z1;
    g_bx[rank * 6 + 3] = x2; g_bx[rank * 6 + 4] = y2; g_bx[rank * 6 + 5] = z2;
    g_vol[rank] = (x2 - x1 + 1.0f) * (y2 - y1 + 1.0f) * (z2 - z1 + 1.0f);
    float ss = x2 - x1 + 1.0f;
    float xc = x1 + ss * 0.5f, yc = y1 + ss * 0.5f, zc = z1 + ss * 0.5f;
    bool valid = (ss >= 8.0f * scale) && (xc < width) && (yc < height) && (zc < slices);
    if (!valid) atomicOr(&g_invalid[rank >> 6], 1ULL << (rank & 63));
}

#define SM_BYTES 34048
__global__ void __launch_bounds__(NTHR, 1)
k_all(const float4* __restrict__ sc4, const float* __restrict__ deltas,
      const float* __restrict__ imi, const float* __restrict__ anchors,
      float* __restrict__ out) {
    __shared__ __align__(16) char smraw[SM_BYTES];
    __shared__ u32 ws[32];
    __shared__ u32 sres[2];
    __shared__ u32 pr[32];
    const int tid = threadIdx.x;
    const int bid = blockIdx.x;
    const int lane = tid & 31;
    const int i0 = bid * NTHR + tid;
    const bool third = (bid < THIRD_BLKS);

    // ---------------- P1: coarse 12-bit histogram ----------------
    {
        u32* sh = (u32*)smraw;
        for (int i = tid; i < 4096; i += NTHR) sh[i] = 0u;
        __syncthreads();
        float4 v0 = sc4[i0];
        float4 v1 = sc4[i0 + GSTRIDE];
        float4 v2 = third ? sc4[i0 + 2 * GSTRIDE] : make_float4(0, 0, 0, 0);
        float f[12] = {v0.x, v0.y, v0.z, v0.w, v1.x, v1.y, v1.z, v1.w,
                       v2.x, v2.y, v2.z, v2.w};
        int nf = third ? 12 : 8;
#pragma unroll
        for (int j = 0; j < 12; j++) {
            if (j >= nf) break;
            u32 b = fkey(f[j]) >> 20;
            u32 m = __match_any_sync(0xFFFFFFFFu, b);
            if ((__ffs(m) - 1) == lane) atomicAdd(&sh[b], __popc(m));
        }
        __syncthreads();
        for (int i = tid; i < 4096; i += NTHR)
            if (sh[i]) atomicAdd(&g_hist1[i], sh[i]);
    }
    gbar();   // G1

    // ---------------- P2: find1 (all blocks) + refined histogram ----------------
    u32 b1, above1;
    {
        u32* sh = (u32*)smraw;
        for (int i = tid; i < 4096; i += NTHR) sh[i] = 0u;
        __syncthreads();
        find_bucket(g_hist1, PRE_TOPN, ws, sres, b1, above1);
        float4 v0 = sc4[i0];
        float4 v1 = sc4[i0 + GSTRIDE];
        float4 v2 = third ? sc4[i0 + 2 * GSTRIDE] : make_float4(0, 0, 0, 0);
        float f[12] = {v0.x, v0.y, v0.z, v0.w, v1.x, v1.y, v1.z, v1.w,
                       v2.x, v2.y, v2.z, v2.w};
        int nf = third ? 12 : 8;
#pragma unroll
        for (int j = 0; j < 12; j++) {
            if (j >= nf) break;
            u32 k = fkey(f[j]);
            if ((k >> 20) == b1) atomicAdd(&sh[(k >> 8) & 0xFFFu], 1u);
        }
        __syncthreads();
        for (int i = tid; i < 4096; i += NTHR)
            if (sh[i]) atomicAdd(&g_hist2[i], sh[i]);
    }
    gbar();   // G2

    // ---------------- P3: find2 (all blocks) + gather; init g_invalid ----------------
    {
        u32 b2, dummy;
        find_bucket(g_hist2, PRE_TOPN - above1, ws, sres, b2, dummy);
        u32 thr = (b1 << 12) | b2;
        if (bid == 0 && tid < 32)
            g_invalid[tid] = (tid == 31) ? 0xFFFFFFFFFFFF0000ULL : 0ULL;
        float4 v0 = sc4[i0];
        float4 v1 = sc4[i0 + GSTRIDE];
        float4 v2 = third ? sc4[i0 + 2 * GSTRIDE] : make_float4(0, 0, 0, 0);
        float f[12] = {v0.x, v0.y, v0.z, v0.w, v1.x, v1.y, v1.z, v1.w,
                       v2.x, v2.y, v2.z, v2.w};
        int bidx[3] = {i0 * 4, (i0 + GSTRIDE) * 4, (i0 + 2 * GSTRIDE) * 4};
        int nf = third ? 12 : 8;
#pragma unroll
        for (int j = 0; j < 12; j++) {
            if (j >= nf) break;
            u32 k = fkey(f[j]);
            bool pred = ((k >> 8) >= thr);
            u32 bal = __ballot_sync(0xFFFFFFFFu, pred);
            if (bal) {
                int leader = __ffs(bal) - 1;
                int posb = 0;
                if (lane == leader) posb = atomicAdd(&g_ccount, __popc(bal));
                posb = __shfl_sync(0xFFFFFFFFu, posb, leader);
                if (pred) {
                    int m = bidx[j >> 2] + (j & 3);
                    int a = m >> 19;
                    int shw = m & (SHW - 1);
                    u32 r = (u32)(shw * A_NUM + a);
                    int pos = posb + __popc(bal & ((1u << lane) - 1u));
                    if (pos < CAND_CAP)
                        g_cand[pos] = ((u64)k << 32) | (0xFFFFFFFFu - r);
                }
            }
        }
    }
    gbar();   // G3

    // ---------------- P4: DISTRIBUTED rank + decode; zero hists ----------------
    {
        int cc = g_ccount; if (cc > CAND_CAP) cc = CAND_CAP;
        u64* st = (u64*)smraw;                 // 2048 u64
        const int grp = tid >> 6;              // 0..15
        const int l64 = tid & 63;
        int c = bid * CPB + grp;
        bool act = (c < cc);
        u64 myk = act ? g_cand[c] : 0ULL;
        u32 partial = 0;
        for (int b0 = 0; b0 < cc; b0 += 2048) {
            int n = min(2048, cc - b0);
            for (int j = tid; j < n; j += NTHR) st[j] = g_cand[b0 + j];
            __syncthreads();
            if (act)
                for (int j = l64; j < n; j += 64) partial += (st[j] > myk);
            __syncthreads();
        }
        // reduce 64 partials per candidate: warp sum -> pr[32] -> pair sum
#pragma unroll
        for (int off = 16; off > 0; off >>= 1)
            partial += __shfl_xor_sync(0xFFFFFFFFu, partial, off);
        if (lane == 0) pr[tid >> 5] = partial;
        __syncthreads();
        if (tid < CPB) {
            int c2 = bid * CPB + tid;
            if (c2 < cc) {
                int rank = (int)(pr[2 * tid] + pr[2 * tid + 1]);
                if (rank < PRE_TOPN)
                    decode_box(g_cand[c2], rank, deltas, imi, anchors);
            }
        }
        // zero histograms for next replay (blocks 0-3 hit each array once)
        for (int i = i0; i < 4096; i += GSTRIDE) { g_hist1[i] = 0u; g_hist2[i] = 0u; }
    }
    gbar();   // G4

    // ---------------- P5: IoU masks; inactive tiles write zeros ----------------
    {
        if (bid == 0 && tid == 0) g_ccount = 0;
        float* cbb = (float*)smraw + (tid >> 6) * 64 * 7;
        int grp = tid >> 6, lt = tid & 63;
        int tile = bid * 16 + grp;
        int rb = tile >> 5, cbi = tile & 31;
        bool act  = (tile < 1024) && (cbi >= rb);
        bool zero = (tile < 1024) && (cbi < rb);
        if (act) {
            int j = cbi * 64 + lt;
            if (j < PRE_TOPN) {
#pragma unroll
                for (int q = 0; q < 6; q++) cbb[lt * 7 + q] = g_bx[j * 6 + q];
                cbb[lt * 7 + 6] = g_vol[j];
            }
        }
        __syncthreads();
        if (zero) {
            int i = rb * 64 + lt;
            if (i < PRE_TOPN) g_mask[i * MASK_COLS + cbi] = 0ULL;
        }
        if (act) {
            int i = rb * 64 + lt;
            if (i < PRE_TOPN) {
                float x1 = g_bx[i * 6 + 0], y1 = g_bx[i * 6 + 1], z1 = g_bx[i * 6 + 2];
                float x2 = g_bx[i * 6 + 3], y2 = g_bx[i * 6 + 4], z2 = g_bx[i * 6 + 5];
                float vi = g_vol[i];
                u64 word = 0ULL;
                int jn = min(64, PRE_TOPN - cbi * 64);
                for (int jj = 0; jj < jn; jj++) {
                    int jg = cbi * 64 + jj;
                    if (jg <= i) continue;
                    const float* cj = cbb + jj * 7;
                    float iw  = fminf(x2, cj[3]) - fmaxf(x1, cj[0]) + 1.0f;
                    float ih  = fminf(y2, cj[4]) - fmaxf(y1, cj[1]) + 1.0f;
                    float idd = fminf(z2, cj[5]) - fmaxf(z1, cj[2]) + 1.0f;
                    iw = fmaxf(iw, 0.0f); ih = fmaxf(ih, 0.0f); idd = fmaxf(idd, 0.0f);
                    float inter = iw * ih * idd;
                    float iou = inter / (vi + cj[6] - inter);
                    if (iou > NMS_T) word |= (1ULL << jj);
                }
                g_mask[i * MASK_COLS + cbi] = word;
            }
        }
    }
    gbar();   // G5

    // ---------------- P6: greedy NMS + output (block 0) ----------------
    if (bid != 0) return;
    {
        u64* buf    = (u64*)smraw;                 // 2 x 2048 u64
        int* keep_s = (int*)(smraw + 32768);
        int* s_nk   = (int*)(smraw + 32768 + 1200);
        int* s_flag = (int*)(smraw + 32768 + 1204);
        if (tid == 0) { *s_flag = 0; *s_nk = 0; }
        u64 remv = 0ULL;
        if (tid < 32) remv = g_invalid[tid];
        for (int k = tid; k < 64 * MASK_COLS; k += NTHR) buf[k] = g_mask[k];
        __syncthreads();

        int nk = 0;
        for (int c = 0; c < MASK_COLS; c++) {
            if (tid >= 32 && c + 1 < MASK_COLS) {
                int r0n = (c + 1) * 64;
                int rnn = min(64, PRE_TOPN - r0n);
                u64* dst = buf + ((c + 1) & 1) * 2048;
                for (int k = tid - 32; k < rnn * MASK_COLS; k += (NTHR - 32))
                    dst[k] = g_mask[r0n * MASK_COLS + k];
            }
            if (tid < 32) {
                const u64* sb = buf + (c & 1) * 2048;
                u64 cur = __shfl_sync(0xFFFFFFFFu, remv, c);
                u64 pend = ~cur;
                while (pend && nk < POST_TOPN) {
                    int b = __ffsll((long long)pend) - 1;
                    if (tid == 0) keep_s[nk] = c * 64 + b;
                    nk++;
                    u64 m  = sb[b * MASK_COLS + tid];
                    u64 mc = sb[b * MASK_COLS + c];
                    remv |= m;
                    pend &= ~mc;
                    pend &= ~(1ULL << b);
                }
                if (tid == 0 && (nk >= POST_TOPN || c == MASK_COLS - 1)) {
                    *s_nk = nk; *s_flag = 1;
                }
            }
            __syncthreads();
            if (*s_flag) break;
        }

        int nkf = *s_nk;
        float* rois = out;
        float* sc   = out + POST_TOPN * 7;
        float* ki   = out + POST_TOPN * 7 + POST_TOPN;
        float* sv   = out + POST_TOPN * 7 + 2 * POST_TOPN;
        for (int p = tid; p < POST_TOPN; p += NTHR) {
            if (p < nkf) {
                int i = keep_s[p];
                rois[p * 7 + 0] = 0.0f;
#pragma unroll
                for (int q = 0; q < 6; q++) rois[p * 7 + 1 + q] = g_bx[i * 6 + q];
                sc[p] = g_score[i];
                ki[p] = (float)g_order[i];
                sv[p] = 1.0f;
            } else {
#pragma unroll
                for (int q = 0; q < 7; q++) rois[p * 7 + q] = 0.0f;
                sc[p] = 0.0f;
                ki[p] = -1.0f;
                sv[p] = 0.0f;
            }
        }
    }
}

extern "C" void kernel_launch(void* const* d_in, const int* in_sizes, int n_in,
                              void* d_out, int out_size) {
    const float4* scores = (const float4*)d_in[0];
    const float*  deltas = (const float*)d_in[1];
    const float*  im_info = (const float*)d_in[2];
    const float*  anchors = (const float*)d_in[3];
    float* out = (float*)d_out;
    k_all<<<NBLK, NTHR>>>(scores, deltas, im_info, anchors, out);
    (void)in_sizes; (void)n_in; (void)out_size;
}